// round 3
// baseline (speedup 1.0000x reference)
#include <cuda_runtime.h>
#include <cstdint>

#define NS 65536
#define D  32
#define R  128
#define S  8
#define WPB 8

typedef unsigned long long ull;

#define OFF_W  0
#define OFF_V  16384
#define OFF_C  32768
#define OFF_B  49152
#define OFF_X  49664
#define SMEM_BYTES (49664 + WPB * D * S * 8)

__device__ float gW[D * R];
__device__ float gV[D * R];
__device__ float gC[D * R];
__device__ float gBias[R];

__global__ void anfis_precomp(const float* __restrict__ a,
                              const float* __restrict__ b,
                              const float* __restrict__ c) {
    int r = blockIdx.x, d = threadIdx.x;
    float av = a[r * D + d];
    float bv = fmaxf(b[r * D + d], 1e-8f);
    float w  = 0.70710678118654752f / bv;
    gW[d * R + r] = w;
    gV[d * R + r] = -w * av;
    gC[d * R + r] = c[r * (D + 1) + d];
    if (d == 0) gBias[r] = c[r * (D + 1) + D];
}

__device__ __forceinline__ ull fma2(ull a, ull b, ull c) {
    ull d;
    asm("fma.rn.f32x2 %0, %1, %2, %3;" : "=l"(d) : "l"(a), "l"(b), "l"(c));
    return d;
}
__device__ __forceinline__ void lds128(uint32_t addr, ull& lo, ull& hi) {
    asm volatile("ld.shared.v2.u64 {%0, %1}, [%2];" : "=l"(lo), "=l"(hi) : "r"(addr));
}
__device__ __forceinline__ void sts64(uint32_t addr, float lo, float hi) {
    asm volatile("st.shared.v2.f32 [%0], {%1, %2};" :: "r"(addr), "f"(lo), "f"(hi));
}
__device__ __forceinline__ void unpack2(ull v, float& lo, float& hi) {
    asm("mov.b64 {%0, %1}, %2;" : "=f"(lo), "=f"(hi) : "l"(v));
}

__global__ void __launch_bounds__(256, 3)
anfis_main(const float* __restrict__ X,
           float* __restrict__ pred,
           float* __restrict__ strengths,
           float* __restrict__ normalized) {
    extern __shared__ float smem[];
    uint32_t sbase;
    {
        uint64_t t;
        asm("cvta.to.shared.u64 %0, %1;" : "=l"(t) : "l"(smem));
        sbase = (uint32_t)t;
    }

    for (int i = threadIdx.x; i < D * R; i += blockDim.x) {
        smem[OFF_W / 4 + i] = gW[i];
        smem[OFF_V / 4 + i] = gV[i];
        smem[OFF_C / 4 + i] = gC[i];
    }
    if (threadIdx.x < R) smem[OFF_B / 4 + threadIdx.x] = gBias[threadIdx.x];
    __syncthreads();

    const int lane  = threadIdx.x & 31;
    const int warp  = threadIdx.x >> 5;
    const int rb    = lane * 4;
    const uint32_t wA = sbase + OFF_W + rb * 4;
    const uint32_t vA = sbase + OFF_V + rb * 4;
    const uint32_t cA = sbase + OFF_C + rb * 4;
    const uint32_t xA = sbase + OFF_X + warp * (D * S * 8);

    const int g  = blockIdx.x * WPB + warp;
    const int n0 = g * S;

    {
        #pragma unroll
        for (int half = 0; half < 2; half++) {
            int j   = lane + half * 32;
            int row = j >> 3;
            int seg = j & 7;
            float4 v = *reinterpret_cast<const float4*>(X + (n0 + row) * D + seg * 4);
            uint32_t base = xA + ((seg * 4) * S + row) * 8;
            sts64(base + 0 * S * 8, v.x, v.x);
            sts64(base + 1 * S * 8, v.y, v.y);
            sts64(base + 2 * S * 8, v.z, v.z);
            sts64(base + 3 * S * 8, v.w, v.w);
        }
        __syncwarp();
    }

    // ===== PASS 1: Gaussian exponents =====
    ull ag[S][2];
    #pragma unroll
    for (int s = 0; s < S; s++) { ag[s][0] = 0ull; ag[s][1] = 0ull; }

    #pragma unroll 8
    for (int d = 0; d < D; d++) {
        ull w01, w23, v01, v23;
        lds128(wA + d * (R * 4), w01, w23);
        lds128(vA + d * (R * 4), v01, v23);
        #pragma unroll
        for (int p = 0; p < S / 2; p++) {
            ull xa, xb;
            lds128(xA + (d * S + 2 * p) * 8, xa, xb);
            ull ua0 = fma2(w01, xa, v01);
            ull ua1 = fma2(w23, xa, v23);
            ag[2 * p][0] = fma2(ua0, ua0, ag[2 * p][0]);
            ag[2 * p][1] = fma2(ua1, ua1, ag[2 * p][1]);
            ull ub0 = fma2(w01, xb, v01);
            ull ub1 = fma2(w23, xb, v23);
            ag[2 * p + 1][0] = fma2(ub0, ub0, ag[2 * p + 1][0]);
            ag[2 * p + 1][1] = fma2(ub1, ub1, ag[2 * p + 1][1]);
        }
    }

    float tsum[S];
    #pragma unroll
    for (int s = 0; s < S; s++) {
        float e0, e1, e2, e3;
        unpack2(ag[s][0], e0, e1);
        unpack2(ag[s][1], e2, e3);
        float s0 = __expf(-e0), s1 = __expf(-e1);
        float s2 = __expf(-e2), s3 = __expf(-e3);
        float t = (s0 + s1) + (s2 + s3);
        #pragma unroll
        for (int off = 16; off > 0; off >>= 1)
            t += __shfl_xor_sync(0xffffffffu, t, off);
        const float inv = 1.0f / (t + 1e-8f);
        const int base = (n0 + s) * R + rb;
        *reinterpret_cast<float4*>(&strengths[base])  = make_float4(s0, s1, s2, s3);
        *reinterpret_cast<float4*>(&normalized[base]) =
            make_float4(s0 * inv, s1 * inv, s2 * inv, s3 * inv);
        tsum[s] = inv;   // kept only so compiler may CSE; unused afterwards
    }
    (void)tsum;

    // ===== PASS 2: linear consequents =====
    ull bb01, bb23;
    lds128(sbase + OFF_B + rb * 4, bb01, bb23);
    ull al[S][2];
    #pragma unroll
    for (int s = 0; s < S; s++) { al[s][0] = bb01; al[s][1] = bb23; }

    #pragma unroll 8
    for (int d = 0; d < D; d++) {
        ull c01, c23;
        lds128(cA + d * (R * 4), c01, c23);
        #pragma unroll
        for (int p = 0; p < S / 2; p++) {
            ull xa, xb;
            lds128(xA + (d * S + 2 * p) * 8, xa, xb);
            al[2 * p][0]     = fma2(c01, xa, al[2 * p][0]);
            al[2 * p][1]     = fma2(c23, xa, al[2 * p][1]);
            al[2 * p + 1][0] = fma2(c01, xb, al[2 * p + 1][0]);
            al[2 * p + 1][1] = fma2(c23, xb, al[2 * p + 1][1]);
        }
    }

    #pragma unroll
    for (int s = 0; s < S; s++) {
        const int base = (n0 + s) * R + rb;
        float4 nm = *reinterpret_cast<const float4*>(&normalized[base]);
        float r0, r1, r2, r3;
        unpack2(al[s][0], r0, r1);
        unpack2(al[s][1], r2, r3);
        float t = (nm.x * r0 + nm.y * r1) + (nm.z * r2 + nm.w * r3);
        #pragma unroll
        for (int off = 16; off > 0; off >>= 1)
            t += __shfl_xor_sync(0xffffffffu, t, off);
        if (lane == 0) pred[n0 + s] = t;
    }
}

extern "C" void kernel_launch(void* const* d_in, const int* in_sizes, int n_in,
                              void* d_out, int out_size) {
    const float* X = (const float*)d_in[0];
    const float* a = (const float*)d_in[1];
    const float* b = (const float*)d_in[2];
    const float* c = (const float*)d_in[3];

    float* out        = (float*)d_out;
    float* pred       = out;
    float* strengths  = out + NS;
    float* normalized = out + NS + NS * R;

    static bool attr_set = false;
    if (!attr_set) {
        cudaFuncSetAttribute(anfis_main,
                             cudaFuncAttributeMaxDynamicSharedMemorySize,
                             SMEM_BYTES);
        attr_set = true;
    }

    anfis_precomp<<<R, D>>>(a, b, c);
    anfis_main<<<NS / S / WPB, 256, SMEM_BYTES>>>(X, pred, strengths, normalized);
}